// round 11
// baseline (speedup 1.0000x reference)
#include <cuda_runtime.h>
#include <cstdint>
#include <cstddef>

// Problem constants
static constexpr int kB = 64;
static constexpr int kL = 1024;
static constexpr int kE = 1024;   // ENC
static constexpr int kA = 1024;   // ATT
static constexpr int kM = kB * kL;

// Scores-GEMM tiling
static constexpr int MT = 128;          // M tile per CTA
static constexpr int NT = 128;          // N tile per pass
static constexpr int KT = 32;           // K tile
static constexpr int NB = kA / NT;      // 8 N passes
static constexpr int KTILES = kE / KT;  // 32

static constexpr int AST = 36;          // A smem row stride (floats): bank = (4r+c)%32, conflict-free
static constexpr int BST = 136;         // B smem row stride (floats): bank = (8k+n)%32, conflict-free
static constexpr int SM_A = 2 * MT * AST;   // double-buffered A
static constexpr int SM_B = 2 * KT * BST;   // double-buffered B
static constexpr int SMEM_FLOATS = SM_A + SM_B + kA /*cbias*/ + kA /*vw*/ + MT /*srow*/;
static constexpr int SMEM_BYTES = SMEM_FLOATS * 4;   // ~80 KB -> dynamic smem

// Scratch (allocation-free rule: device globals)
__device__ float g_ph[kB * kA];
__device__ float g_scores[kB * kL];

// ---------------------------------------------------------------------------
// helpers
// ---------------------------------------------------------------------------
__device__ __forceinline__ void cp16(float* sdst, const float* gsrc) {
    uint32_t s = (uint32_t)__cvta_generic_to_shared(sdst);
    asm volatile("cp.async.cg.shared.global [%0], [%1], 16;\n" :: "r"(s), "l"(gsrc));
}
__device__ __forceinline__ void cp_commit() {
    asm volatile("cp.async.commit_group;\n");
}
template <int N>
__device__ __forceinline__ void cp_wait() {
    asm volatile("cp.async.wait_group %0;\n" :: "n"(N));
}

// m16n8k8 tf32 MMA, D = A*B + D (fp32 accum). Raw fp32 bits in A/B regs:
// HW uses the tf32 subset of the mantissa (truncation, ~2^-11 rel).
__device__ __forceinline__ void mma_tf32(float* d, const uint32_t* a, uint32_t b0, uint32_t b1) {
    asm volatile(
        "mma.sync.aligned.m16n8k8.row.col.f32.tf32.tf32.f32 "
        "{%0,%1,%2,%3}, {%4,%5,%6,%7}, {%8,%9}, {%0,%1,%2,%3};\n"
        : "+f"(d[0]), "+f"(d[1]), "+f"(d[2]), "+f"(d[3])
        : "r"(a[0]), "r"(a[1]), "r"(a[2]), "r"(a[3]), "r"(b0), "r"(b1));
}

// ---------------------------------------------------------------------------
// 1) proj_h[b,n] = sum_k hidden[b,k] * W2[k,n] + b2[n]
// ---------------------------------------------------------------------------
__global__ void proj_h_kernel(const float* __restrict__ hidden,
                              const float* __restrict__ W2w,
                              const float* __restrict__ W2b) {
    __shared__ float sh[kA];
    const int b = blockIdx.x;
    const int n = threadIdx.x;
    sh[n] = hidden[b * kA + n];   // DEC == 1024 == blockDim.x
    __syncthreads();
    float acc = 0.f;
#pragma unroll 8
    for (int k = 0; k < kE; ++k)
        acc = fmaf(sh[k], W2w[k * kA + n], acc);
    g_ph[b * kA + n] = acc + W2b[n];
}

// ---------------------------------------------------------------------------
// 2) fused scores GEMM:
//    score[m] = sum_n tanh( (features[m,:]@W1)[n] + W1b[n] + ph[b,n] ) * Vw[n] + Vb
// CTA: 128 rows, 256 threads (8 warps = 4M x 2N). For each of 8 N-blocks of 128
// columns, run the full K loop (cp.async double-buffered), then fold tanh*V into
// per-thread score registers. A tile is re-read per N-block (L2-resident).
// ---------------------------------------------------------------------------
__global__ void __launch_bounds__(256)
scores_kernel(const float* __restrict__ features,
              const float* __restrict__ W1w,
              const float* __restrict__ W1b,
              const float* __restrict__ Vw,
              const float* __restrict__ Vb) {
    extern __shared__ float smem[];
    float* sA    = smem;                    // [2][MT][AST]
    float* sB    = smem + SM_A;             // [2][KT][BST]
    float* cbias = smem + SM_A + SM_B;      // [kA]  W1b[n] + ph[b,n]
    float* vw    = cbias + kA;              // [kA]
    float* srow  = vw + kA;                 // [MT]  per-row score accumulation

    const int tid = threadIdx.x;
    const int m_base = blockIdx.x * MT;
    const int b = m_base / kL;              // MT divides L -> single batch per CTA

    for (int i = tid; i < kA; i += 256) {
        cbias[i] = W1b[i] + g_ph[b * kA + i];
        vw[i] = Vw[i];
    }
    if (tid < MT) srow[tid] = 0.f;
    __syncthreads();

    const int warp = tid >> 5, lane = tid & 31;
    const int wm = warp >> 1;   // 0..3 -> M offset wm*32
    const int wn = warp & 1;    // 0..1 -> N offset wn*64
    const int qr = lane >> 2;   // groupID
    const int qc = lane & 3;    // threadID-in-group

    // global->smem copy lanes
    const int a_r0 = tid >> 3, a_c4 = (tid & 7) * 4;   // A: 128x32, 4 rows/thread
    const int b_r0 = tid >> 5, b_c4 = (tid & 31) * 4;  // B: 32x128, 4 rows/thread

    const float* gA = features + (size_t)m_base * kE;

    float sc[2][2] = {{0.f, 0.f}, {0.f, 0.f}};  // [m-tile][row-half]

    for (int nb = 0; nb < NB; ++nb) {
        const int n0 = nb * NT;
        const float* gBp = W1w + n0;

        float acc[2][8][4];
#pragma unroll
        for (int mt = 0; mt < 2; ++mt)
#pragma unroll
            for (int nt = 0; nt < 8; ++nt)
#pragma unroll
                for (int f = 0; f < 4; ++f) acc[mt][nt][f] = 0.f;

        // prologue: stage kt=0 into buffer 0
        {
#pragma unroll
            for (int i = 0; i < 4; ++i) {
                const int r = a_r0 + i * 32;
                cp16(&sA[r * AST + a_c4], gA + (size_t)r * kE + a_c4);
            }
#pragma unroll
            for (int i = 0; i < 4; ++i) {
                const int r = b_r0 + i * 8;
                cp16(&sB[r * BST + b_c4], gBp + (size_t)r * kA + b_c4);
            }
            cp_commit();
        }

        for (int kt = 0; kt < KTILES; ++kt) {
            const int buf = kt & 1;
            if (kt + 1 < KTILES) {
                const int k0 = (kt + 1) * KT;
                float* dA = sA + (buf ^ 1) * MT * AST;
#pragma unroll
                for (int i = 0; i < 4; ++i) {
                    const int r = a_r0 + i * 32;
                    cp16(&dA[r * AST + a_c4], gA + (size_t)r * kE + k0 + a_c4);
                }
                float* dB = sB + (buf ^ 1) * KT * BST;
#pragma unroll
                for (int i = 0; i < 4; ++i) {
                    const int r = b_r0 + i * 8;
                    cp16(&dB[r * BST + b_c4], gBp + (size_t)(k0 + r) * kA + b_c4);
                }
                cp_commit();
                cp_wait<1>();   // current tile's group complete, next may be in flight
            } else {
                cp_wait<0>();
            }
            __syncthreads();

            const float* cA = sA + buf * MT * AST;
            const float* cB = sB + buf * KT * BST;
#pragma unroll
            for (int ks = 0; ks < 4; ++ks) {
                uint32_t a[2][4];
#pragma unroll
                for (int mt = 0; mt < 2; ++mt) {
                    const uint32_t* p =
                        (const uint32_t*)(cA + (wm * 32 + mt * 16 + qr) * AST + ks * 8 + qc);
                    a[mt][0] = p[0];
                    a[mt][1] = p[8 * AST];
                    a[mt][2] = p[4];
                    a[mt][3] = p[8 * AST + 4];
                }
#pragma unroll
                for (int nt = 0; nt < 8; ++nt) {
                    const uint32_t* p =
                        (const uint32_t*)(cB + (ks * 8 + qc) * BST + wn * 64 + nt * 8 + qr);
                    const uint32_t b0 = p[0];
                    const uint32_t b1 = p[4 * BST];
                    mma_tf32(acc[0][nt], a[0], b0, b1);
                    mma_tf32(acc[1][nt], a[1], b0, b1);
                }
            }
            __syncthreads();
        }

        // epilogue: tanh + dot with V, fold into per-thread score accumulators
#pragma unroll
        for (int mt = 0; mt < 2; ++mt) {
#pragma unroll
            for (int nt = 0; nt < 8; ++nt) {
                const int n = n0 + wn * 64 + nt * 8 + qc * 2;
                const float c0 = cbias[n], c1 = cbias[n + 1];
                const float v0 = vw[n], v1 = vw[n + 1];
                sc[mt][0] += tanhf(acc[mt][nt][0] + c0) * v0;
                sc[mt][0] += tanhf(acc[mt][nt][1] + c1) * v1;
                sc[mt][1] += tanhf(acc[mt][nt][2] + c0) * v0;
                sc[mt][1] += tanhf(acc[mt][nt][3] + c1) * v1;
            }
        }
    }

    // reduce over the 4 column-threads of each quad, then across the 2 N-warps
#pragma unroll
    for (int mt = 0; mt < 2; ++mt)
#pragma unroll
        for (int h = 0; h < 2; ++h) {
            float v = sc[mt][h];
            v += __shfl_xor_sync(0xffffffffu, v, 1);
            v += __shfl_xor_sync(0xffffffffu, v, 2);
            if (qc == 0) atomicAdd(&srow[wm * 32 + mt * 16 + h * 8 + qr], v);
        }
    __syncthreads();
    if (tid < MT) g_scores[m_base + tid] = srow[tid] + Vb[0];
}

// ---------------------------------------------------------------------------
// 3) softmax over L per batch -> alpha (written to d_out[0 : B*L])
// ---------------------------------------------------------------------------
__global__ void softmax_kernel(float* __restrict__ alpha) {
    const int b = blockIdx.x;
    const int tid = threadIdx.x;
    const float* s = g_scores + b * kL;

    float v[4];
    float m = -1e30f;
#pragma unroll
    for (int i = 0; i < 4; ++i) {
        v[i] = s[tid + i * 256];
        m = fmaxf(m, v[i]);
    }
#pragma unroll
    for (int o = 16; o > 0; o >>= 1) m = fmaxf(m, __shfl_xor_sync(0xffffffffu, m, o));
    __shared__ float redm[8];
    __shared__ float reds[8];
    if ((tid & 31) == 0) redm[tid >> 5] = m;
    __syncthreads();
    m = redm[0];
#pragma unroll
    for (int i = 1; i < 8; ++i) m = fmaxf(m, redm[i]);

    float sum = 0.f;
#pragma unroll
    for (int i = 0; i < 4; ++i) {
        v[i] = expf(v[i] - m);
        sum += v[i];
    }
#pragma unroll
    for (int o = 16; o > 0; o >>= 1) sum += __shfl_xor_sync(0xffffffffu, sum, o);
    if ((tid & 31) == 0) reds[tid >> 5] = sum;
    __syncthreads();
    sum = 0.f;
#pragma unroll
    for (int i = 0; i < 8; ++i) sum += reds[i];
    const float inv = 1.f / sum;
#pragma unroll
    for (int i = 0; i < 4; ++i) alpha[b * kL + tid + i * 256] = v[i] * inv;
}

// ---------------------------------------------------------------------------
// 4) context[b,e] = sum_l alpha[b,l] * features[b,l,e]
// ---------------------------------------------------------------------------
__global__ void context_kernel(const float* __restrict__ features,
                               const float* __restrict__ alpha,
                               float* __restrict__ ctx) {
    const int b = blockIdx.y;
    const int e = blockIdx.x * 256 + threadIdx.x;
    __shared__ float sa[kL];
    for (int i = threadIdx.x; i < kL; i += 256) sa[i] = alpha[b * kL + i];
    __syncthreads();
    const float* f = features + (size_t)b * kL * kE + e;
    float acc = 0.f;
#pragma unroll 8
    for (int l = 0; l < kL; ++l)
        acc = fmaf(sa[l], f[(size_t)l * kE], acc);
    ctx[b * kE + e] = acc;
}

// ---------------------------------------------------------------------------
// launch
// ---------------------------------------------------------------------------
extern "C" void kernel_launch(void* const* d_in, const int* in_sizes, int n_in,
                              void* d_out, int out_size) {
    (void)in_sizes; (void)n_in; (void)out_size;
    const float* features = (const float*)d_in[0];   // [B, L, ENC]
    const float* hidden   = (const float*)d_in[1];   // [B, DEC]
    const float* W1w      = (const float*)d_in[2];   // [ENC, ATT]
    const float* W1b      = (const float*)d_in[3];   // [ATT]
    const float* W2w      = (const float*)d_in[4];   // [DEC, ATT]
    const float* W2b      = (const float*)d_in[5];   // [ATT]
    const float* Vw       = (const float*)d_in[6];   // [ATT]
    const float* Vb       = (const float*)d_in[7];   // scalar

    float* out   = (float*)d_out;
    float* alpha = out;            // [B, L]
    float* ctx   = out + kB * kL;  // [B, ENC]

    // idempotent, capture-safe (no graph node)
    cudaFuncSetAttribute(scores_kernel, cudaFuncAttributeMaxDynamicSharedMemorySize, SMEM_BYTES);

    proj_h_kernel<<<kB, 1024>>>(hidden, W2w, W2b);
    scores_kernel<<<kM / MT, 256, SMEM_BYTES>>>(features, W1w, W1b, Vw, Vb);
    softmax_kernel<<<kB, 256>>>(alpha);
    context_kernel<<<dim3(kE / 256, kB), 256>>>(features, alpha, ctx);
}

// round 12
// speedup vs baseline: 1.0457x; 1.0457x over previous
#include <cuda_runtime.h>
#include <cuda_fp16.h>
#include <cstdint>
#include <cstddef>

// Problem constants
static constexpr int kB = 64;
static constexpr int kL = 1024;
static constexpr int kE = 1024;   // ENC
static constexpr int kA = 1024;   // ATT
static constexpr int kM = kB * kL;

// Scores-GEMM tiling
static constexpr int MT = 128;          // M tile per CTA
static constexpr int NT = 128;          // N tile per pass
static constexpr int KT = 32;           // K tile
static constexpr int NB = kA / NT;      // 8 N passes
static constexpr int KTILES = kE / KT;  // 32

static constexpr int AST = 36;          // A smem row stride (floats): conflict-free
static constexpr int BST = 136;         // B smem row stride (floats): conflict-free
static constexpr int SM_A = 2 * MT * AST;   // double-buffered A
static constexpr int SM_B = 2 * KT * BST;   // double-buffered B
// cbias/vw now packed half2 (kA/2 u32 words each)
static constexpr int SMEM_FLOATS = SM_A + SM_B + kA / 2 + kA / 2 + MT;
static constexpr int SMEM_BYTES = SMEM_FLOATS * 4;

// Scratch (allocation-free rule: device globals)
__device__ float g_ph[kB * kA];
__device__ float g_scores[kB * kL];
__device__ float g_cpart[8 * kB * kE];   // context partials: [chunk][b][e]

// ---------------------------------------------------------------------------
// helpers
// ---------------------------------------------------------------------------
__device__ __forceinline__ void cp16(float* sdst, const float* gsrc) {
    uint32_t s = (uint32_t)__cvta_generic_to_shared(sdst);
    asm volatile("cp.async.cg.shared.global [%0], [%1], 16;\n" :: "r"(s), "l"(gsrc));
}
__device__ __forceinline__ void cp_commit() {
    asm volatile("cp.async.commit_group;\n");
}
template <int N>
__device__ __forceinline__ void cp_wait() {
    asm volatile("cp.async.wait_group %0;\n" :: "n"(N));
}

// m16n8k8 tf32 MMA, D = A*B + D (fp32 accum). Raw fp32 bits in A/B regs.
__device__ __forceinline__ void mma_tf32(float* d, const uint32_t* a, uint32_t b0, uint32_t b1) {
    asm volatile(
        "mma.sync.aligned.m16n8k8.row.col.f32.tf32.tf32.f32 "
        "{%0,%1,%2,%3}, {%4,%5,%6,%7}, {%8,%9}, {%0,%1,%2,%3};\n"
        : "+f"(d[0]), "+f"(d[1]), "+f"(d[2]), "+f"(d[3])
        : "r"(a[0]), "r"(a[1]), "r"(a[2]), "r"(a[3]), "r"(b0), "r"(b1));
}

// Packed epilogue: for adjacent columns (n, n+1):
//   returns tanh(d0 + c_lo)*v_lo + tanh(d1 + c_hi)*v_hi
// Uses tanh.approx.f16x2 (1 MUFU per 2 elements).
__device__ __forceinline__ float tanhv2(float d0, float d1, uint32_t ch, uint32_t vh) {
    uint32_t x, t, p;
    asm("cvt.rn.f16x2.f32 %0, %1, %2;" : "=r"(x) : "f"(d1), "f"(d0)); // lo=d0, hi=d1
    asm("add.rn.f16x2 %0, %0, %1;" : "+r"(x) : "r"(ch));
    asm("tanh.approx.f16x2 %0, %1;" : "=r"(t) : "r"(x));
    asm("mul.rn.f16x2 %0, %1, %2;" : "=r"(p) : "r"(t), "r"(vh));
    __half2 h = *reinterpret_cast<__half2*>(&p);
    float2 f = __half22float2(h);
    return f.x + f.y;
}

// ---------------------------------------------------------------------------
// 1) proj_h[b,n] = sum_k hidden[b,k] * W2[k,n] + b2[n]
// ---------------------------------------------------------------------------
__global__ void proj_h_kernel(const float* __restrict__ hidden,
                              const float* __restrict__ W2w,
                              const float* __restrict__ W2b) {
    __shared__ float sh[kA];
    const int b = blockIdx.x;
    const int n = threadIdx.x;
    sh[n] = hidden[b * kA + n];
    __syncthreads();
    float acc = 0.f;
#pragma unroll 8
    for (int k = 0; k < kE; ++k)
        acc = fmaf(sh[k], W2w[k * kA + n], acc);
    g_ph[b * kA + n] = acc + W2b[n];
}

// ---------------------------------------------------------------------------
// 2) fused scores GEMM (tf32 MMA) + packed half2 tanh*V epilogue
// ---------------------------------------------------------------------------
__global__ void __launch_bounds__(256)
scores_kernel(const float* __restrict__ features,
              const float* __restrict__ W1w,
              const float* __restrict__ W1b,
              const float* __restrict__ Vw,
              const float* __restrict__ Vb) {
    extern __shared__ float smem[];
    float* sA = smem;                                   // [2][MT][AST]
    float* sB = smem + SM_A;                            // [2][KT][BST]
    uint32_t* cbias_h2 = (uint32_t*)(smem + SM_A + SM_B);   // [kA/2] half2(W1b+ph)
    uint32_t* vw_h2    = cbias_h2 + kA / 2;                 // [kA/2] half2(Vw)
    float* srow = (float*)(vw_h2 + kA / 2);                 // [MT]

    const int tid = threadIdx.x;
    const int m_base = blockIdx.x * MT;
    const int b = m_base / kL;

    {
        const float2* wb2 = (const float2*)W1b;
        const float2* ph2 = (const float2*)(g_ph + b * kA);
        const float2* vw2 = (const float2*)Vw;
        for (int i = tid; i < kA / 2; i += 256) {
            float2 wb = wb2[i], ph = ph2[i], vv = vw2[i];
            __half2 hc = __floats2half2_rn(wb.x + ph.x, wb.y + ph.y);
            __half2 hv = __floats2half2_rn(vv.x, vv.y);
            cbias_h2[i] = *(uint32_t*)&hc;
            vw_h2[i]    = *(uint32_t*)&hv;
        }
    }
    if (tid < MT) srow[tid] = 0.f;
    __syncthreads();

    const int warp = tid >> 5, lane = tid & 31;
    const int wm = warp >> 1;   // 0..3 -> M offset wm*32
    const int wn = warp & 1;    // 0..1 -> N offset wn*64
    const int qr = lane >> 2;   // groupID
    const int qc = lane & 3;    // threadID-in-group

    const int a_r0 = tid >> 3, a_c4 = (tid & 7) * 4;   // A: 128x32
    const int b_r0 = tid >> 5, b_c4 = (tid & 31) * 4;  // B: 32x128

    const float* gA = features + (size_t)m_base * kE;

    float sc[2][2] = {{0.f, 0.f}, {0.f, 0.f}};

    for (int nb = 0; nb < NB; ++nb) {
        const int n0 = nb * NT;
        const float* gBp = W1w + n0;

        float acc[2][8][4];
#pragma unroll
        for (int mt = 0; mt < 2; ++mt)
#pragma unroll
            for (int nt = 0; nt < 8; ++nt)
#pragma unroll
                for (int f = 0; f < 4; ++f) acc[mt][nt][f] = 0.f;

        // prologue: stage kt=0 into buffer 0
        {
#pragma unroll
            for (int i = 0; i < 4; ++i) {
                const int r = a_r0 + i * 32;
                cp16(&sA[r * AST + a_c4], gA + (size_t)r * kE + a_c4);
            }
#pragma unroll
            for (int i = 0; i < 4; ++i) {
                const int r = b_r0 + i * 8;
                cp16(&sB[r * BST + b_c4], gBp + (size_t)r * kA + b_c4);
            }
            cp_commit();
        }

        for (int kt = 0; kt < KTILES; ++kt) {
            const int buf = kt & 1;
            if (kt + 1 < KTILES) {
                const int k0 = (kt + 1) * KT;
                float* dA = sA + (buf ^ 1) * MT * AST;
#pragma unroll
                for (int i = 0; i < 4; ++i) {
                    const int r = a_r0 + i * 32;
                    cp16(&dA[r * AST + a_c4], gA + (size_t)r * kE + k0 + a_c4);
                }
                float* dB = sB + (buf ^ 1) * KT * BST;
#pragma unroll
                for (int i = 0; i < 4; ++i) {
                    const int r = b_r0 + i * 8;
                    cp16(&dB[r * BST + b_c4], gBp + (size_t)(k0 + r) * kA + b_c4);
                }
                cp_commit();
                cp_wait<1>();
            } else {
                cp_wait<0>();
            }
            __syncthreads();

            const float* cA = sA + buf * MT * AST;
            const float* cB = sB + buf * KT * BST;
#pragma unroll
            for (int ks = 0; ks < 4; ++ks) {
                uint32_t a[2][4];
#pragma unroll
                for (int mt = 0; mt < 2; ++mt) {
                    const uint32_t* p =
                        (const uint32_t*)(cA + (wm * 32 + mt * 16 + qr) * AST + ks * 8 + qc);
                    a[mt][0] = p[0];
                    a[mt][1] = p[8 * AST];
                    a[mt][2] = p[4];
                    a[mt][3] = p[8 * AST + 4];
                }
#pragma unroll
                for (int nt = 0; nt < 8; ++nt) {
                    const uint32_t* p =
                        (const uint32_t*)(cB + (ks * 8 + qc) * BST + wn * 64 + nt * 8 + qr);
                    const uint32_t b0 = p[0];
                    const uint32_t b1 = p[4 * BST];
                    mma_tf32(acc[0][nt], a[0], b0, b1);
                    mma_tf32(acc[1][nt], a[1], b0, b1);
                }
            }
            __syncthreads();
        }

        // epilogue: packed tanh + dot with V
#pragma unroll
        for (int mt = 0; mt < 2; ++mt) {
#pragma unroll
            for (int nt = 0; nt < 8; ++nt) {
                const int nh = (n0 + wn * 64 + nt * 8 + qc * 2) >> 1;
                const uint32_t ch = cbias_h2[nh];
                const uint32_t vh = vw_h2[nh];
                sc[mt][0] += tanhv2(acc[mt][nt][0], acc[mt][nt][1], ch, vh);
                sc[mt][1] += tanhv2(acc[mt][nt][2], acc[mt][nt][3], ch, vh);
            }
        }
    }

    // reduce over quad columns, then across the 2 N-warps via smem atomics
#pragma unroll
    for (int mt = 0; mt < 2; ++mt)
#pragma unroll
        for (int h = 0; h < 2; ++h) {
            float v = sc[mt][h];
            v += __shfl_xor_sync(0xffffffffu, v, 1);
            v += __shfl_xor_sync(0xffffffffu, v, 2);
            if (qc == 0) atomicAdd(&srow[wm * 32 + mt * 16 + h * 8 + qr], v);
        }
    __syncthreads();
    if (tid < MT) g_scores[m_base + tid] = srow[tid] + Vb[0];
}

// ---------------------------------------------------------------------------
// 3) softmax over L per batch -> alpha
// ---------------------------------------------------------------------------
__global__ void softmax_kernel(float* __restrict__ alpha) {
    const int b = blockIdx.x;
    const int tid = threadIdx.x;
    const float* s = g_scores + b * kL;

    float v[4];
    float m = -1e30f;
#pragma unroll
    for (int i = 0; i < 4; ++i) {
        v[i] = s[tid + i * 256];
        m = fmaxf(m, v[i]);
    }
#pragma unroll
    for (int o = 16; o > 0; o >>= 1) m = fmaxf(m, __shfl_xor_sync(0xffffffffu, m, o));
    __shared__ float redm[8];
    __shared__ float reds[8];
    if ((tid & 31) == 0) redm[tid >> 5] = m;
    __syncthreads();
    m = redm[0];
#pragma unroll
    for (int i = 1; i < 8; ++i) m = fmaxf(m, redm[i]);

    float sum = 0.f;
#pragma unroll
    for (int i = 0; i < 4; ++i) {
        v[i] = expf(v[i] - m);
        sum += v[i];
    }
#pragma unroll
    for (int o = 16; o > 0; o >>= 1) sum += __shfl_xor_sync(0xffffffffu, sum, o);
    if ((tid & 31) == 0) reds[tid >> 5] = sum;
    __syncthreads();
    sum = 0.f;
#pragma unroll
    for (int i = 0; i < 8; ++i) sum += reds[i];
    const float inv = 1.f / sum;
#pragma unroll
    for (int i = 0; i < 4; ++i) alpha[b * kL + tid + i * 256] = v[i] * inv;
}

// ---------------------------------------------------------------------------
// 4a) context partials: chunk of 128 l-values per CTA, float4 per thread
// ---------------------------------------------------------------------------
__global__ void __launch_bounds__(256)
context_part_kernel(const float* __restrict__ features,
                    const float* __restrict__ alpha) {
    const int chunk = blockIdx.x;   // 0..7
    const int b = blockIdx.y;
    __shared__ float sa[128];
    if (threadIdx.x < 128) sa[threadIdx.x] = alpha[b * kL + chunk * 128 + threadIdx.x];
    __syncthreads();
    const float4* f =
        (const float4*)(features + ((size_t)b * kL + chunk * 128) * kE) + threadIdx.x;
    float4 acc = make_float4(0.f, 0.f, 0.f, 0.f);
#pragma unroll 8
    for (int l = 0; l < 128; ++l) {
        float4 v = f[(size_t)l * (kE / 4)];
        const float a = sa[l];
        acc.x = fmaf(a, v.x, acc.x);
        acc.y = fmaf(a, v.y, acc.y);
        acc.z = fmaf(a, v.z, acc.z);
        acc.w = fmaf(a, v.w, acc.w);
    }
    ((float4*)(g_cpart + ((size_t)chunk * kB + b) * kE))[threadIdx.x] = acc;
}

// 4b) reduce the 8 partials -> context
__global__ void context_reduce_kernel(float* __restrict__ ctx) {
    const int b = blockIdx.y;
    const int e = blockIdx.x * 256 + threadIdx.x;
    float s = 0.f;
#pragma unroll
    for (int c = 0; c < 8; ++c) s += g_cpart[((size_t)c * kB + b) * kE + e];
    ctx[b * kE + e] = s;
}

// ---------------------------------------------------------------------------
// launch
// ---------------------------------------------------------------------------
extern "C" void kernel_launch(void* const* d_in, const int* in_sizes, int n_in,
                              void* d_out, int out_size) {
    (void)in_sizes; (void)n_in; (void)out_size;
    const float* features = (const float*)d_in[0];   // [B, L, ENC]
    const float* hidden   = (const float*)d_in[1];   // [B, DEC]
    const float* W1w      = (const float*)d_in[2];   // [ENC, ATT]
    const float* W1b      = (const float*)d_in[3];   // [ATT]
    const float* W2w      = (const float*)d_in[4];   // [DEC, ATT]
    const float* W2b      = (const float*)d_in[5];   // [ATT]
    const float* Vw       = (const float*)d_in[6];   // [ATT]
    const float* Vb       = (const float*)d_in[7];   // scalar

    float* out   = (float*)d_out;
    float* alpha = out;            // [B, L]
    float* ctx   = out + kB * kL;  // [B, ENC]

    cudaFuncSetAttribute(scores_kernel, cudaFuncAttributeMaxDynamicSharedMemorySize, SMEM_BYTES);

    proj_h_kernel<<<kB, 1024>>>(hidden, W2w, W2b);
    scores_kernel<<<kM / MT, 256, SMEM_BYTES>>>(features, W1w, W1b, Vw, Vb);
    softmax_kernel<<<kB, 256>>>(alpha);
    context_part_kernel<<<dim3(8, kB), 256>>>(features, alpha);
    context_reduce_kernel<<<dim3(kE / 256, kB), 256>>>(ctx);
}

// round 15
// speedup vs baseline: 1.7658x; 1.6887x over previous
#include <cuda_runtime.h>
#include <cuda_fp16.h>
#include <cstdint>
#include <cstddef>

// Problem constants
static constexpr int kB = 64;
static constexpr int kL = 1024;
static constexpr int kE = 1024;   // ENC
static constexpr int kA = 1024;   // ATT
static constexpr int kM = kB * kL;

// Scores-GEMM tiling (fp16 legacy mma m16n8k16)
static constexpr int MT = 128;          // M tile per CTA
static constexpr int NT = 128;          // N tile per pass
static constexpr int KT = 64;           // K per smem tile (halfs)
static constexpr int NB = kA / NT;      // 8 N passes
static constexpr int KTILES = kE / KT;  // 16

static constexpr int ROW_BYTES = 144;               // smem row stride (bytes): bank = 4*row+chunk, conflict-free
static constexpr uint32_t TILE_B = 128 * ROW_BYTES; // 18432 B per tile
static constexpr uint32_t SA_OFF = 0;               // 2 A tiles
static constexpr uint32_t SB_OFF = 2 * TILE_B;      // 2 B tiles
static constexpr uint32_t CB_OFF = 4 * TILE_B;      // 2KB half2(W1b+ph)
static constexpr uint32_t VW_OFF = CB_OFF + 2048;   // 2KB half2(Vw)
static constexpr uint32_t SROW_OFF = VW_OFF + 2048; // 512B
static constexpr uint32_t SC_SMEM = SROW_OFF + 512; // ~78.3 KB

// Scratch (allocation-free rule: device globals)
__device__ __half g_fA[(size_t)kM * kE];     // features fp16 (128 MB)
__device__ __half g_W1t[(size_t)kA * kE];    // W1 transposed, n-major, fp16 (2 MB)
__device__ float  g_ph[kB * kA];
__device__ float  g_scores[kB * kL];
__device__ float  g_cpart[8 * kB * kE];      // context partials [chunk][b][e]

// ---------------------------------------------------------------------------
// helpers
// ---------------------------------------------------------------------------
__device__ __forceinline__ void cp16(void* sdst, const void* gsrc) {
    uint32_t s;
    asm("{ .reg .u64 t; cvta.to.shared.u64 t, %1; cvt.u32.u64 %0, t; }" : "=r"(s) : "l"(sdst));
    asm volatile("cp.async.cg.shared.global [%0], [%1], 16;\n" :: "r"(s), "l"(gsrc));
}
__device__ __forceinline__ void cp_commit() { asm volatile("cp.async.commit_group;\n"); }
template <int N>
__device__ __forceinline__ void cp_wait() { asm volatile("cp.async.wait_group %0;\n" :: "n"(N)); }

// m16n8k16 fp16 MMA, fp32 accumulate: D += A(16x16 row) * B(16x8 col)
__device__ __forceinline__ void mma_f16(float* d, const uint32_t* a, uint32_t b0, uint32_t b1) {
    asm volatile(
        "mma.sync.aligned.m16n8k16.row.col.f32.f16.f16.f32 "
        "{%0,%1,%2,%3}, {%4,%5,%6,%7}, {%8,%9}, {%0,%1,%2,%3};\n"
        : "+f"(d[0]), "+f"(d[1]), "+f"(d[2]), "+f"(d[3])
        : "r"(a[0]), "r"(a[1]), "r"(a[2]), "r"(a[3]), "r"(b0), "r"(b1));
}

// Packed tanh epilogue: tanh(d0+c_lo)*v_lo + tanh(d1+c_hi)*v_hi (1 MUFU per 2 cols)
__device__ __forceinline__ float tanhv2(float d0, float d1, uint32_t ch, uint32_t vh) {
    uint32_t x, t, p;
    asm("cvt.rn.f16x2.f32 %0, %1, %2;" : "=r"(x) : "f"(d1), "f"(d0));
    asm("add.rn.f16x2 %0, %0, %1;" : "+r"(x) : "r"(ch));
    asm("tanh.approx.f16x2 %0, %1;" : "=r"(t) : "r"(x));
    asm("mul.rn.f16x2 %0, %1, %2;" : "=r"(p) : "r"(t), "r"(vh));
    __half2 h = *reinterpret_cast<__half2*>(&p);
    float2 f = __half22float2(h);
    return f.x + f.y;
}

// ---------------------------------------------------------------------------
// 0a) features fp32 -> fp16
// ---------------------------------------------------------------------------
__global__ void conv_feat_kernel(const float4* __restrict__ f) {
    const size_t n4 = (size_t)kM * kE / 4;
    uint2* dst = reinterpret_cast<uint2*>(g_fA);
    for (size_t i = (size_t)blockIdx.x * blockDim.x + threadIdx.x; i < n4;
         i += (size_t)gridDim.x * blockDim.x) {
        float4 v = f[i];
        __half2 a = __floats2half2_rn(v.x, v.y);
        __half2 b = __floats2half2_rn(v.z, v.w);
        dst[i] = make_uint2(*(uint32_t*)&a, *(uint32_t*)&b);
    }
}

// 0b) W1 [k][n] fp32 -> W1t [n][k] fp16
__global__ void conv_w1t_kernel(const float* __restrict__ W1w) {
    __shared__ float t[32][33];
    const int k0 = blockIdx.y * 32, n0 = blockIdx.x * 32;
    t[threadIdx.y][threadIdx.x] = W1w[(size_t)(k0 + threadIdx.y) * kA + n0 + threadIdx.x];
    __syncthreads();
    g_W1t[(size_t)(n0 + threadIdx.y) * kE + k0 + threadIdx.x] =
        __float2half(t[threadIdx.x][threadIdx.y]);
}

// ---------------------------------------------------------------------------
// 1) proj_h[b,n] = hidden[b,:] @ W2[:,n] + b2[n]
// ---------------------------------------------------------------------------
__global__ void proj_h_kernel(const float* __restrict__ hidden,
                              const float* __restrict__ W2w,
                              const float* __restrict__ W2b) {
    __shared__ float sh[kA];
    const int b = blockIdx.x;
    const int n = threadIdx.x;
    sh[n] = hidden[b * kA + n];
    __syncthreads();
    float acc = 0.f;
#pragma unroll 8
    for (int k = 0; k < kE; ++k)
        acc = fmaf(sh[k], W2w[(size_t)k * kA + n], acc);
    g_ph[b * kA + n] = acc + W2b[n];
}

// ---------------------------------------------------------------------------
// 2) fused scores GEMM (fp16 m16n8k16, fp32 accum) + packed tanh*V epilogue
//    CTA: 128 rows x 256 threads (8 warps = 4M x 2N warp grid).
// ---------------------------------------------------------------------------
__device__ __forceinline__ void load_tile(char* smem, uint32_t base,
                                          const __half* g, int k0, int tid) {
    // 128 rows x 64 halfs; 1024 x 16B chunks; 4 per thread
#pragma unroll
    for (int i = 0; i < 4; ++i) {
        const int idx = tid + i * 256;
        const int r = idx >> 3, c = idx & 7;
        cp16(smem + base + (uint32_t)r * ROW_BYTES + c * 16,
             g + (size_t)r * kE + k0 + c * 8);
    }
}

__global__ void __launch_bounds__(256)
scores_kernel(const float* __restrict__ W1b,
              const float* __restrict__ Vw,
              const float* __restrict__ Vb) {
    extern __shared__ char smem[];
    uint32_t* cb = (uint32_t*)(smem + CB_OFF);
    uint32_t* vw = (uint32_t*)(smem + VW_OFF);
    float* srow  = (float*)(smem + SROW_OFF);

    const int tid = threadIdx.x;
    const int m_base = blockIdx.x * MT;
    const int b = m_base >> 10;

    {
        const float2* wb2 = (const float2*)W1b;
        const float2* ph2 = (const float2*)(g_ph + b * kA);
        const float2* vv2 = (const float2*)Vw;
        for (int i = tid; i < kA / 2; i += 256) {
            float2 a = wb2[i], p = ph2[i], v = vv2[i];
            __half2 hc = __floats2half2_rn(a.x + p.x, a.y + p.y);
            __half2 hv = __floats2half2_rn(v.x, v.y);
            cb[i] = *(uint32_t*)&hc;
            vw[i] = *(uint32_t*)&hv;
        }
    }
    if (tid < MT) srow[tid] = 0.f;
    __syncthreads();

    const int warp = tid >> 5, lane = tid & 31;
    const int wm = warp >> 1;   // 0..3 -> M offset wm*32
    const int wn = warp & 1;    // 0..1 -> N offset wn*64
    const int qr = lane >> 2;   // groupID (0..7)
    const int qc = lane & 3;    // threadID-in-group

    const __half* gA = g_fA + (size_t)m_base * kE;

    float sc[2][2] = {{0.f, 0.f}, {0.f, 0.f}};

    for (int nb = 0; nb < NB; ++nb) {
        const int n0 = nb * NT;
        const __half* gB = g_W1t + (size_t)n0 * kE;

        float acc[2][8][4];
#pragma unroll
        for (int mt = 0; mt < 2; ++mt)
#pragma unroll
            for (int nt = 0; nt < 8; ++nt)
#pragma unroll
                for (int f = 0; f < 4; ++f) acc[mt][nt][f] = 0.f;

        // prologue: k-tile 0 -> buffer 0
        load_tile(smem, SA_OFF, gA, 0, tid);
        load_tile(smem, SB_OFF, gB, 0, tid);
        cp_commit();

        for (int kt = 0; kt < KTILES; ++kt) {
            const int buf = kt & 1;
            if (kt + 1 < KTILES) {
                const int k0 = (kt + 1) * KT;
                load_tile(smem, SA_OFF + (buf ^ 1) * TILE_B, gA, k0, tid);
                load_tile(smem, SB_OFF + (buf ^ 1) * TILE_B, gB, k0, tid);
                cp_commit();
                cp_wait<1>();   // current tile's group complete
            } else {
                cp_wait<0>();
            }
            __syncthreads();

            const char* cA = smem + SA_OFF + buf * TILE_B;
            const char* cB = smem + SB_OFF + buf * TILE_B;
#pragma unroll
            for (int ks = 0; ks < 4; ++ks) {
                uint32_t a[2][4];
#pragma unroll
                for (int mt = 0; mt < 2; ++mt) {
                    const char* p = cA + (wm * 32 + mt * 16 + qr) * ROW_BYTES + ks * 32 + qc * 4;
                    a[mt][0] = *(const uint32_t*)(p);
                    a[mt][1] = *(const uint32_t*)(p + 8 * ROW_BYTES);
                    a[mt][2] = *(const uint32_t*)(p + 16);
                    a[mt][3] = *(const uint32_t*)(p + 8 * ROW_BYTES + 16);
                }
#pragma unroll
                for (int nt = 0; nt < 8; ++nt) {
                    const char* p = cB + (wn * 64 + nt * 8 + qr) * ROW_BYTES + ks * 32 + qc * 4;
                    const uint32_t b0 = *(const uint32_t*)(p);
                    const uint32_t b1 = *(const uint32_t*)(p + 16);
                    mma_f16(acc[0][nt], a[0], b0, b1);
                    mma_f16(acc[1][nt], a[1], b0, b1);
                }
            }
            __syncthreads();
        }

        // epilogue: packed tanh + dot with V
#pragma unroll
        for (int mt = 0; mt < 2; ++mt) {
#pragma unroll
            for (int nt = 0; nt < 8; ++nt) {
                const int nh = (n0 + wn * 64 + nt * 8 + qc * 2) >> 1;
                const uint32_t ch = cb[nh];
                const uint32_t vh = vw[nh];
                sc[mt][0] += tanhv2(acc[mt][nt][0], acc[mt][nt][1], ch, vh);
                sc[mt][1] += tanhv2(acc[mt][nt][2], acc[mt][nt][3], ch, vh);
            }
        }
    }

    // reduce over quad columns, then across the 2 N-warps via smem atomics
#pragma unroll
    for (int mt = 0; mt < 2; ++mt)
#pragma unroll
        for (int h = 0; h < 2; ++h) {
            float v = sc[mt][h];
            v += __shfl_xor_sync(0xffffffffu, v, 1);
            v += __shfl_xor_sync(0xffffffffu, v, 2);
            if (qc == 0) atomicAdd(&srow[wm * 32 + mt * 16 + h * 8 + qr], v);
        }
    __syncthreads();
    if (tid < MT) g_scores[m_base + tid] = srow[tid] + Vb[0];
}

// ---------------------------------------------------------------------------
// 3) softmax over L per batch -> alpha
// ---------------------------------------------------------------------------
__global__ void softmax_kernel(float* __restrict__ alpha) {
    const int b = blockIdx.x;
    const int tid = threadIdx.x;
    const float* s = g_scores + b * kL;

    float v[4];
    float m = -1e30f;
#pragma unroll
    for (int i = 0; i < 4; ++i) {
        v[i] = s[tid + i * 256];
        m = fmaxf(m, v[i]);
    }
#pragma unroll
    for (int o = 16; o > 0; o >>= 1) m = fmaxf(m, __shfl_xor_sync(0xffffffffu, m, o));
    __shared__ float redm[8];
    __shared__ float reds[8];
    if ((tid & 31) == 0) redm[tid >> 5] = m;
    __syncthreads();
    m = redm[0];
#pragma unroll
    for (int i = 1; i < 8; ++i) m = fmaxf(m, redm[i]);

    float sum = 0.f;
#pragma unroll
    for (int i = 0; i < 4; ++i) {
        v[i] = expf(v[i] - m);
        sum += v[i];
    }
#pragma unroll
    for (int o = 16; o > 0; o >>= 1) sum += __shfl_xor_sync(0xffffffffu, sum, o);
    if ((tid & 31) == 0) reds[tid >> 5] = sum;
    __syncthreads();
    sum = 0.f;
#pragma unroll
    for (int i = 0; i < 8; ++i) sum += reds[i];
    const float inv = 1.f / sum;
#pragma unroll
    for (int i = 0; i < 4; ++i) alpha[b * kL + tid + i * 256] = v[i] * inv;
}

// ---------------------------------------------------------------------------
// 4a) context partials from fp16 features: 128 l-values per CTA
// ---------------------------------------------------------------------------
__global__ void __launch_bounds__(128)
context_part_kernel(const float* __restrict__ alpha) {
    const int chunk = blockIdx.x;   // 0..7
    const int b = blockIdx.y;
    __shared__ float sa[128];
    sa[threadIdx.x] = alpha[b * kL + chunk * 128 + threadIdx.x];
    __syncthreads();
    const uint4* f =
        (const uint4*)(g_fA + ((size_t)b * kL + chunk * 128) * kE) + threadIdx.x;
    float acc[8] = {0.f, 0.f, 0.f, 0.f, 0.f, 0.f, 0.f, 0.f};
#pragma unroll 4
    for (int l = 0; l < 128; ++l) {
        uint4 v = f[(size_t)l * (kE / 8)];
        const float a = sa[l];
        const __half2* h = (const __half2*)&v;
#pragma unroll
        for (int j = 0; j < 4; ++j) {
            float2 p = __half22float2(h[j]);
            acc[2 * j]     = fmaf(a, p.x, acc[2 * j]);
            acc[2 * j + 1] = fmaf(a, p.y, acc[2 * j + 1]);
        }
    }
    float* out = g_cpart + ((size_t)chunk * kB + b) * kE + threadIdx.x * 8;
    ((float4*)out)[0] = make_float4(acc[0], acc[1], acc[2], acc[3]);
    ((float4*)out)[1] = make_float4(acc[4], acc[5], acc[6], acc[7]);
}

// 4b) reduce the 8 partials -> context
__global__ void context_reduce_kernel(float* __restrict__ ctx) {
    const int b = blockIdx.y;
    const int e = blockIdx.x * 256 + threadIdx.x;
    float s = 0.f;
#pragma unroll
    for (int c = 0; c < 8; ++c) s += g_cpart[((size_t)c * kB + b) * kE + e];
    ctx[b * kE + e] = s;
}

// ---------------------------------------------------------------------------
// launch
// ---------------------------------------------------------------------------
extern "C" void kernel_launch(void* const* d_in, const int* in_sizes, int n_in,
                              void* d_out, int out_size) {
    (void)in_sizes; (void)n_in; (void)out_size;
    const float* features = (const float*)d_in[0];   // [B, L, ENC]
    const float* hidden   = (const float*)d_in[1];   // [B, DEC]
    const float* W1w      = (const float*)d_in[2];   // [ENC, ATT]
    const float* W1b      = (const float*)d_in[3];   // [ATT]
    const float* W2w      = (const float*)d_in[4];   // [DEC, ATT]
    const float* W2b      = (const float*)d_in[5];   // [ATT]
    const float* Vw       = (const float*)d_in[6];   // [ATT]
    const float* Vb       = (const float*)d_in[7];   // scalar

    float* out   = (float*)d_out;
    float* alpha = out;            // [B, L]
    float* ctx   = out + kB * kL;  // [B, ENC]

    cudaFuncSetAttribute(scores_kernel, cudaFuncAttributeMaxDynamicSharedMemorySize, SC_SMEM);

    conv_feat_kernel<<<4096, 256>>>((const float4*)features);
    conv_w1t_kernel<<<dim3(kA / 32, kE / 32), dim3(32, 32)>>>(W1w);
    proj_h_kernel<<<kB, 1024>>>(hidden, W2w, W2b);
    scores_kernel<<<kM / MT, 256, SC_SMEM>>>(W1b, Vw, Vb);
    softmax_kernel<<<kB, 256>>>(alpha);
    context_part_kernel<<<dim3(8, kB), 128>>>(alpha);
    context_reduce_kernel<<<dim3(kE / 256, kB), 256>>>(ctx);
}

// round 16
// speedup vs baseline: 1.8125x; 1.0265x over previous
#include <cuda_runtime.h>
#include <cuda_fp16.h>
#include <cstdint>
#include <cstddef>

// Problem constants
static constexpr int kB = 64;
static constexpr int kL = 1024;
static constexpr int kE = 1024;   // ENC
static constexpr int kA = 1024;   // ATT
static constexpr int kM = kB * kL;

// Scores-GEMM tiling (fp16 legacy mma m16n8k16)
static constexpr int MT = 128;          // M tile per CTA
static constexpr int NT = 128;          // N tile per pass
static constexpr int KT = 64;           // K per smem tile (halfs)
static constexpr int NB = kA / NT;      // 8 N passes
static constexpr int KTILES = kE / KT;  // 16

static constexpr int ROW_BYTES = 144;               // smem row stride: bank = 4*row+chunk, conflict-free
static constexpr uint32_t TILE_B = 128 * ROW_BYTES; // 18432 B per tile
static constexpr uint32_t SA_OFF = 0;               // 2 A tiles
static constexpr uint32_t SB_OFF = 2 * TILE_B;      // 2 B tiles
static constexpr uint32_t CB_OFF = 4 * TILE_B;      // 2KB half2(W1b+ph)
static constexpr uint32_t VW_OFF = CB_OFF + 2048;   // 2KB half2(Vw)
static constexpr uint32_t SROW_OFF = VW_OFF + 2048; // 512B
static constexpr uint32_t SC_SMEM = SROW_OFF + 512; // ~78.3 KB

// Scratch (allocation-free rule: device globals)
__device__ __half g_fA[(size_t)kM * kE];     // features fp16 (128 MB)
__device__ __half g_W1t[(size_t)kA * kE];    // W1 transposed, n-major, fp16 (2 MB)
__device__ float  g_ph[kB * kA];
__device__ float  g_scores[kB * kL];
__device__ float  g_cpart[8 * kB * kE];      // context partials [chunk][b][e]

// ---------------------------------------------------------------------------
// helpers
// ---------------------------------------------------------------------------
__device__ __forceinline__ uint32_t smem_u32(const void* p) {
    uint32_t a;
    asm("{ .reg .u64 t; cvta.to.shared.u64 t, %1; cvt.u32.u64 %0, t; }" : "=r"(a) : "l"(p));
    return a;
}
__device__ __forceinline__ void cp16(void* sdst, const void* gsrc) {
    uint32_t s = smem_u32(sdst);
    asm volatile("cp.async.cg.shared.global [%0], [%1], 16;\n" :: "r"(s), "l"(gsrc));
}
__device__ __forceinline__ void cp_commit() { asm volatile("cp.async.commit_group;\n"); }
template <int N>
__device__ __forceinline__ void cp_wait() { asm volatile("cp.async.wait_group %0;\n" :: "n"(N)); }

// ldmatrix x4: 4 independent 8x8 b16 matrices; thread r in [8m,8m+8) supplies
// the address of row r&7 of matrix m. After load, thread i holds row i/4,
// cols (i%4)*2..+1 of each matrix.
__device__ __forceinline__ void ldsm4(uint32_t& r0, uint32_t& r1, uint32_t& r2, uint32_t& r3,
                                      uint32_t saddr) {
    asm volatile("ldmatrix.sync.aligned.m8n8.x4.shared.b16 {%0,%1,%2,%3}, [%4];"
                 : "=r"(r0), "=r"(r1), "=r"(r2), "=r"(r3) : "r"(saddr));
}

// m16n8k16 fp16 MMA, fp32 accumulate
__device__ __forceinline__ void mma_f16(float* d, const uint32_t* a, uint32_t b0, uint32_t b1) {
    asm volatile(
        "mma.sync.aligned.m16n8k16.row.col.f32.f16.f16.f32 "
        "{%0,%1,%2,%3}, {%4,%5,%6,%7}, {%8,%9}, {%0,%1,%2,%3};\n"
        : "+f"(d[0]), "+f"(d[1]), "+f"(d[2]), "+f"(d[3])
        : "r"(a[0]), "r"(a[1]), "r"(a[2]), "r"(a[3]), "r"(b0), "r"(b1));
}

// Packed tanh epilogue: tanh(d0+c_lo)*v_lo + tanh(d1+c_hi)*v_hi
__device__ __forceinline__ float tanhv2(float d0, float d1, uint32_t ch, uint32_t vh) {
    uint32_t x, t, p;
    asm("cvt.rn.f16x2.f32 %0, %1, %2;" : "=r"(x) : "f"(d1), "f"(d0));
    asm("add.rn.f16x2 %0, %0, %1;" : "+r"(x) : "r"(ch));
    asm("tanh.approx.f16x2 %0, %1;" : "=r"(t) : "r"(x));
    asm("mul.rn.f16x2 %0, %1, %2;" : "=r"(p) : "r"(t), "r"(vh));
    __half2 h = *reinterpret_cast<__half2*>(&p);
    float2 f = __half22float2(h);
    return f.x + f.y;
}

// ---------------------------------------------------------------------------
// 0a) features fp32 -> fp16
// ---------------------------------------------------------------------------
__global__ void conv_feat_kernel(const float4* __restrict__ f) {
    const size_t n4 = (size_t)kM * kE / 4;
    uint2* dst = reinterpret_cast<uint2*>(g_fA);
    for (size_t i = (size_t)blockIdx.x * blockDim.x + threadIdx.x; i < n4;
         i += (size_t)gridDim.x * blockDim.x) {
        float4 v = f[i];
        __half2 a = __floats2half2_rn(v.x, v.y);
        __half2 b = __floats2half2_rn(v.z, v.w);
        dst[i] = make_uint2(*(uint32_t*)&a, *(uint32_t*)&b);
    }
}

// 0b) W1 [k][n] fp32 -> W1t [n][k] fp16
__global__ void conv_w1t_kernel(const float* __restrict__ W1w) {
    __shared__ float t[32][33];
    const int k0 = blockIdx.y * 32, n0 = blockIdx.x * 32;
    t[threadIdx.y][threadIdx.x] = W1w[(size_t)(k0 + threadIdx.y) * kA + n0 + threadIdx.x];
    __syncthreads();
    g_W1t[(size_t)(n0 + threadIdx.y) * kE + k0 + threadIdx.x] =
        __float2half(t[threadIdx.x][threadIdx.y]);
}

// ---------------------------------------------------------------------------
// 1) proj_h[b,n] = hidden[b,:] @ W2[:,n] + b2[n]
// ---------------------------------------------------------------------------
__global__ void proj_h_kernel(const float* __restrict__ hidden,
                              const float* __restrict__ W2w,
                              const float* __restrict__ W2b) {
    __shared__ float sh[kA];
    const int b = blockIdx.x;
    const int n = threadIdx.x;
    sh[n] = hidden[b * kA + n];
    __syncthreads();
    float acc = 0.f;
#pragma unroll 8
    for (int k = 0; k < kE; ++k)
        acc = fmaf(sh[k], W2w[(size_t)k * kA + n], acc);
    g_ph[b * kA + n] = acc + W2b[n];
}

// ---------------------------------------------------------------------------
// 2) fused scores GEMM (fp16 m16n8k16 via ldmatrix) + packed tanh*V epilogue
//    CTA: 128 rows x 256 threads (8 warps = 4M x 2N), 2 CTAs/SM.
// ---------------------------------------------------------------------------
__device__ __forceinline__ void load_tile(char* smem, uint32_t base,
                                          const __half* g, int k0, int tid) {
#pragma unroll
    for (int i = 0; i < 4; ++i) {
        const int idx = tid + i * 256;
        const int r = idx >> 3, c = idx & 7;
        cp16(smem + base + (uint32_t)r * ROW_BYTES + c * 16,
             g + (size_t)r * kE + k0 + c * 8);
    }
}

__global__ void __launch_bounds__(256, 2)
scores_kernel(const float* __restrict__ W1b,
              const float* __restrict__ Vw,
              const float* __restrict__ Vb) {
    extern __shared__ char smem[];
    const uint32_t sbase = smem_u32(smem);
    uint32_t* cb = (uint32_t*)(smem + CB_OFF);
    uint32_t* vw = (uint32_t*)(smem + VW_OFF);
    float* srow  = (float*)(smem + SROW_OFF);

    const int tid = threadIdx.x;
    const int m_base = blockIdx.x * MT;
    const int b = m_base >> 10;

    {
        const float2* wb2 = (const float2*)W1b;
        const float2* ph2 = (const float2*)(g_ph + b * kA);
        const float2* vv2 = (const float2*)Vw;
        for (int i = tid; i < kA / 2; i += 256) {
            float2 a = wb2[i], p = ph2[i], v = vv2[i];
            __half2 hc = __floats2half2_rn(a.x + p.x, a.y + p.y);
            __half2 hv = __floats2half2_rn(v.x, v.y);
            cb[i] = *(uint32_t*)&hc;
            vw[i] = *(uint32_t*)&hv;
        }
    }
    if (tid < MT) srow[tid] = 0.f;
    __syncthreads();

    const int warp = tid >> 5, lane = tid & 31;
    const int wm = warp >> 1;   // 0..3 -> M offset wm*32
    const int wn = warp & 1;    // 0..1 -> N offset wn*64
    const int qc = lane & 3;    // threadID-in-group (epilogue col pair)

    // ldmatrix base addresses (byte offsets into shared space)
    // A (mt tiles): matrices [m0-7,k0][m8-15,k0][m0-7,k8][m8-15,k8]
    uint32_t aAddr[2];
#pragma unroll
    for (int mt = 0; mt < 2; ++mt)
        aAddr[mt] = sbase + SA_OFF +
                    (uint32_t)(wm * 32 + mt * 16 + (lane & 15)) * ROW_BYTES +
                    ((lane >> 4) * 8) * 2;
    // B (nn pairs): matrices [n0-7,k0][n0-7,k8][n8-15,k0][n8-15,k8]
    uint32_t bAddr[4];
#pragma unroll
    for (int nn = 0; nn < 4; ++nn)
        bAddr[nn] = sbase + SB_OFF +
                    (uint32_t)(wn * 64 + nn * 16 + ((lane >> 4) & 1) * 8 + (lane & 7)) * ROW_BYTES +
                    (((lane >> 3) & 1) * 8) * 2;

    const __half* gA = g_fA + (size_t)m_base * kE;

    float sc[2][2] = {{0.f, 0.f}, {0.f, 0.f}};

    for (int nb = 0; nb < NB; ++nb) {
        const int n0 = nb * NT;
        const __half* gB = g_W1t + (size_t)n0 * kE;

        float acc[2][8][4];
#pragma unroll
        for (int mt = 0; mt < 2; ++mt)
#pragma unroll
            for (int nt = 0; nt < 8; ++nt)
#pragma unroll
                for (int f = 0; f < 4; ++f) acc[mt][nt][f] = 0.f;

        // prologue: k-tile 0 -> buffer 0
        load_tile(smem, SA_OFF, gA, 0, tid);
        load_tile(smem, SB_OFF, gB, 0, tid);
        cp_commit();

        for (int kt = 0; kt < KTILES; ++kt) {
            const int buf = kt & 1;
            if (kt + 1 < KTILES) {
                const int k0 = (kt + 1) * KT;
                load_tile(smem, SA_OFF + (buf ^ 1) * TILE_B, gA, k0, tid);
                load_tile(smem, SB_OFF + (buf ^ 1) * TILE_B, gB, k0, tid);
                cp_commit();
                cp_wait<1>();
            } else {
                cp_wait<0>();
            }
            __syncthreads();

            const uint32_t bofs = (uint32_t)buf * TILE_B;
#pragma unroll
            for (int ks = 0; ks < 4; ++ks) {
                uint32_t a[2][4];
                ldsm4(a[0][0], a[0][1], a[0][2], a[0][3], aAddr[0] + bofs + ks * 32);
                ldsm4(a[1][0], a[1][1], a[1][2], a[1][3], aAddr[1] + bofs + ks * 32);
#pragma unroll
                for (int nn = 0; nn < 4; ++nn) {
                    uint32_t b0, b1, b2, b3;
                    ldsm4(b0, b1, b2, b3, bAddr[nn] + bofs + ks * 32);
                    mma_f16(acc[0][2 * nn],     a[0], b0, b1);
                    mma_f16(acc[1][2 * nn],     a[1], b0, b1);
                    mma_f16(acc[0][2 * nn + 1], a[0], b2, b3);
                    mma_f16(acc[1][2 * nn + 1], a[1], b2, b3);
                }
            }
            __syncthreads();
        }

        // epilogue: packed tanh + dot with V
#pragma unroll
        for (int mt = 0; mt < 2; ++mt) {
#pragma unroll
            for (int nt = 0; nt < 8; ++nt) {
                const int nh = (n0 + wn * 64 + nt * 8 + qc * 2) >> 1;
                const uint32_t ch = cb[nh];
                const uint32_t vh = vw[nh];
                sc[mt][0] += tanhv2(acc[mt][nt][0], acc[mt][nt][1], ch, vh);
                sc[mt][1] += tanhv2(acc[mt][nt][2], acc[mt][nt][3], ch, vh);
            }
        }
    }

    // reduce over quad columns, then across the 2 N-warps via smem atomics
    const int qr = lane >> 2;
#pragma unroll
    for (int mt = 0; mt < 2; ++mt)
#pragma unroll
        for (int h = 0; h < 2; ++h) {
            float v = sc[mt][h];
            v += __shfl_xor_sync(0xffffffffu, v, 1);
            v += __shfl_xor_sync(0xffffffffu, v, 2);
            if (qc == 0) atomicAdd(&srow[wm * 32 + mt * 16 + h * 8 + qr], v);
        }
    __syncthreads();
    if (tid < MT) g_scores[m_base + tid] = srow[tid] + Vb[0];
}

// ---------------------------------------------------------------------------
// 3) softmax over L per batch -> alpha
// ---------------------------------------------------------------------------
__global__ void softmax_kernel(float* __restrict__ alpha) {
    const int b = blockIdx.x;
    const int tid = threadIdx.x;
    const float* s = g_scores + b * kL;

    float v[4];
    float m = -1e30f;
#pragma unroll
    for (int i = 0; i < 4; ++i) {
        v[i] = s[tid + i * 256];
        m = fmaxf(m, v[i]);
    }
#pragma unroll
    for (int o = 16; o > 0; o >>= 1) m = fmaxf(m, __shfl_xor_sync(0xffffffffu, m, o));
    __shared__ float redm[8];
    __shared__ float reds[8];
    if ((tid & 31) == 0) redm[tid >> 5] = m;
    __syncthreads();
    m = redm[0];
#pragma unroll
    for (int i = 1; i < 8; ++i) m = fmaxf(m, redm[i]);

    float sum = 0.f;
#pragma unroll
    for (int i = 0; i < 4; ++i) {
        v[i] = expf(v[i] - m);
        sum += v[i];
    }
#pragma unroll
    for (int o = 16; o > 0; o >>= 1) sum += __shfl_xor_sync(0xffffffffu, sum, o);
    if ((tid & 31) == 0) reds[tid >> 5] = sum;
    __syncthreads();
    sum = 0.f;
#pragma unroll
    for (int i = 0; i < 8; ++i) sum += reds[i];
    const float inv = 1.f / sum;
#pragma unroll
    for (int i = 0; i < 4; ++i) alpha[b * kL + tid + i * 256] = v[i] * inv;
}

// ---------------------------------------------------------------------------
// 4a) context partials from fp16 features: 128 l-values per CTA
// ---------------------------------------------------------------------------
__global__ void __launch_bounds__(128)
context_part_kernel(const float* __restrict__ alpha) {
    const int chunk = blockIdx.x;   // 0..7
    const int b = blockIdx.y;
    __shared__ float sa[128];
    sa[threadIdx.x] = alpha[b * kL + chunk * 128 + threadIdx.x];
    __syncthreads();
    const uint4* f =
        (const uint4*)(g_fA + ((size_t)b * kL + chunk * 128) * kE) + threadIdx.x;
    float acc[8] = {0.f, 0.f, 0.f, 0.f, 0.f, 0.f, 0.f, 0.f};
#pragma unroll 4
    for (int l = 0; l < 128; ++l) {
        uint4 v = f[(size_t)l * (kE / 8)];
        const float a = sa[l];
        const __half2* h = (const __half2*)&v;
#pragma unroll
        for (int j = 0; j < 4; ++j) {
            float2 p = __half22float2(h[j]);
            acc[2 * j]     = fmaf(a, p.x, acc[2 * j]);
            acc[2 * j + 1] = fmaf(a, p.y, acc[2 * j + 1]);
        }
    }
    float* out = g_cpart + ((size_t)chunk * kB + b) * kE + threadIdx.x * 8;
    ((float4*)out)[0] = make_float4(acc[0], acc[1], acc[2], acc[3]);
    ((float4*)out)[1] = make_float4(acc[4], acc[5], acc[6], acc[7]);
}

// 4b) reduce the 8 partials -> context
__global__ void context_reduce_kernel(float* __restrict__ ctx) {
    const int b = blockIdx.y;
    const int e = blockIdx.x * 256 + threadIdx.x;
    float s = 0.f;
#pragma unroll
    for (int c = 0; c < 8; ++c) s += g_cpart[((size_t)c * kB + b) * kE + e];
    ctx[b * kE + e] = s;
}

// ---------------------------------------------------------------------------
// launch
// ---------------------------------------------------------------------------
extern "C" void kernel_launch(void* const* d_in, const int* in_sizes, int n_in,
                              void* d_out, int out_size) {
    (void)in_sizes; (void)n_in; (void)out_size;
    const float* features = (const float*)d_in[0];   // [B, L, ENC]
    const float* hidden   = (const float*)d_in[1];   // [B, DEC]
    const float* W1w      = (const float*)d_in[2];   // [ENC, ATT]
    const float* W1b      = (const float*)d_in[3];   // [ATT]
    const float* W2w      = (const float*)d_in[4];   // [DEC, ATT]
    const float* W2b      = (const float*)d_in[5];   // [ATT]
    const float* Vw       = (const float*)d_in[6];   // [ATT]
    const float* Vb       = (const float*)d_in[7];   // scalar

    float* out   = (float*)d_out;
    float* alpha = out;            // [B, L]
    float* ctx   = out + kB * kL;  // [B, ENC]

    cudaFuncSetAttribute(scores_kernel, cudaFuncAttributeMaxDynamicSharedMemorySize, SC_SMEM);

    conv_feat_kernel<<<4096, 256>>>((const float4*)features);
    conv_w1t_kernel<<<dim3(kA / 32, kE / 32), dim3(32, 32)>>>(W1w);
    proj_h_kernel<<<kB, 1024>>>(hidden, W2w, W2b);
    scores_kernel<<<kM / MT, 256, SC_SMEM>>>(W1b, Vw, Vb);
    softmax_kernel<<<kB, 256>>>(alpha);
    context_part_kernel<<<dim3(8, kB), 128>>>(alpha);
    context_reduce_kernel<<<dim3(kE / 256, kB), 256>>>(ctx);
}

// round 17
// speedup vs baseline: 1.8134x; 1.0005x over previous
#include <cuda_runtime.h>
#include <cuda_fp16.h>
#include <cstdint>
#include <cstddef>

// Problem constants
static constexpr int kB = 64;
static constexpr int kL = 1024;
static constexpr int kE = 1024;   // ENC
static constexpr int kA = 1024;   // ATT
static constexpr int kM = kB * kL;

// Scores-GEMM tiling (fp16 legacy mma m16n8k16)
static constexpr int MT = 128;          // M tile per CTA
static constexpr int NT = 128;          // N tile per pass
static constexpr int KT = 64;           // K per smem tile (halfs)
static constexpr int NB = kA / NT;      // 8 N passes
static constexpr int KTILES = kE / KT;  // 16

static constexpr int ROW_BYTES = 144;               // smem row stride: bank = 4*row+chunk, conflict-free
static constexpr uint32_t TILE_B = 128 * ROW_BYTES; // 18432 B per tile
static constexpr uint32_t SA_OFF = 0;               // 2 A tiles
static constexpr uint32_t SB_OFF = 2 * TILE_B;      // 2 B tiles
static constexpr uint32_t CB_OFF = 4 * TILE_B;      // 2KB half2(W1b+ph)
static constexpr uint32_t VW_OFF = CB_OFF + 2048;   // 2KB half2(Vw)
static constexpr uint32_t SROW_OFF = VW_OFF + 2048; // 512B
static constexpr uint32_t SC_SMEM = SROW_OFF + 512; // ~78.3 KB

// Scratch (allocation-free rule: device globals)
__device__ __half g_fA[(size_t)kM * kE];     // features fp16 (128 MB)
__device__ __half g_W1t[(size_t)kA * kE];    // W1 transposed, n-major, fp16 (2 MB)
__device__ float  g_ph[kB * kA];
__device__ float  g_scores[kB * kL];
__device__ float  g_cpart[8 * kB * kE];      // context partials [chunk][b][e]

// ---------------------------------------------------------------------------
// helpers
// ---------------------------------------------------------------------------
__device__ __forceinline__ uint32_t smem_u32(const void* p) {
    uint32_t a;
    asm("{ .reg .u64 t; cvta.to.shared.u64 t, %1; cvt.u32.u64 %0, t; }" : "=r"(a) : "l"(p));
    return a;
}
__device__ __forceinline__ void cp16(void* sdst, const void* gsrc) {
    uint32_t s = smem_u32(sdst);
    asm volatile("cp.async.cg.shared.global [%0], [%1], 16;\n" :: "r"(s), "l"(gsrc));
}
__device__ __forceinline__ void cp_commit() { asm volatile("cp.async.commit_group;\n"); }
template <int N>
__device__ __forceinline__ void cp_wait() { asm volatile("cp.async.wait_group %0;\n" :: "n"(N)); }

// ldmatrix x4: 4 independent 8x8 b16 matrices; thread r in [8m,8m+8) supplies
// the address of row r&7 of matrix m. After load, thread i holds row i/4,
// cols (i%4)*2..+1 of each matrix.
__device__ __forceinline__ void ldsm4(uint32_t& r0, uint32_t& r1, uint32_t& r2, uint32_t& r3,
                                      uint32_t saddr) {
    asm volatile("ldmatrix.sync.aligned.m8n8.x4.shared.b16 {%0,%1,%2,%3}, [%4];"
                 : "=r"(r0), "=r"(r1), "=r"(r2), "=r"(r3) : "r"(saddr));
}

// m16n8k16 fp16 MMA, fp32 accumulate
__device__ __forceinline__ void mma_f16(float* d, const uint32_t* a, uint32_t b0, uint32_t b1) {
    asm volatile(
        "mma.sync.aligned.m16n8k16.row.col.f32.f16.f16.f32 "
        "{%0,%1,%2,%3}, {%4,%5,%6,%7}, {%8,%9}, {%0,%1,%2,%3};\n"
        : "+f"(d[0]), "+f"(d[1]), "+f"(d[2]), "+f"(d[3])
        : "r"(a[0]), "r"(a[1]), "r"(a[2]), "r"(a[3]), "r"(b0), "r"(b1));
}

// Packed tanh epilogue: tanh(d0+c_lo)*v_lo + tanh(d1+c_hi)*v_hi
__device__ __forceinline__ float tanhv2(float d0, float d1, uint32_t ch, uint32_t vh) {
    uint32_t x, t, p;
    asm("cvt.rn.f16x2.f32 %0, %1, %2;" : "=r"(x) : "f"(d1), "f"(d0));
    asm("add.rn.f16x2 %0, %0, %1;" : "+r"(x) : "r"(ch));
    asm("tanh.approx.f16x2 %0, %1;" : "=r"(t) : "r"(x));
    asm("mul.rn.f16x2 %0, %1, %2;" : "=r"(p) : "r"(t), "r"(vh));
    __half2 h = *reinterpret_cast<__half2*>(&p);
    float2 f = __half22float2(h);
    return f.x + f.y;
}

// ---------------------------------------------------------------------------
// 0a) features fp32 -> fp16
// ---------------------------------------------------------------------------
__global__ void conv_feat_kernel(const float4* __restrict__ f) {
    const size_t n4 = (size_t)kM * kE / 4;
    uint2* dst = reinterpret_cast<uint2*>(g_fA);
    for (size_t i = (size_t)blockIdx.x * blockDim.x + threadIdx.x; i < n4;
         i += (size_t)gridDim.x * blockDim.x) {
        float4 v = f[i];
        __half2 a = __floats2half2_rn(v.x, v.y);
        __half2 b = __floats2half2_rn(v.z, v.w);
        dst[i] = make_uint2(*(uint32_t*)&a, *(uint32_t*)&b);
    }
}

// 0b) W1 [k][n] fp32 -> W1t [n][k] fp16
__global__ void conv_w1t_kernel(const float* __restrict__ W1w) {
    __shared__ float t[32][33];
    const int k0 = blockIdx.y * 32, n0 = blockIdx.x * 32;
    t[threadIdx.y][threadIdx.x] = W1w[(size_t)(k0 + threadIdx.y) * kA + n0 + threadIdx.x];
    __syncthreads();
    g_W1t[(size_t)(n0 + threadIdx.y) * kE + k0 + threadIdx.x] =
        __float2half(t[threadIdx.x][threadIdx.y]);
}

// ---------------------------------------------------------------------------
// 1) proj_h[b,n] = hidden[b,:] @ W2[:,n] + b2[n]
// ---------------------------------------------------------------------------
__global__ void proj_h_kernel(const float* __restrict__ hidden,
                              const float* __restrict__ W2w,
                              const float* __restrict__ W2b) {
    __shared__ float sh[kA];
    const int b = blockIdx.x;
    const int n = threadIdx.x;
    sh[n] = hidden[b * kA + n];
    __syncthreads();
    float acc = 0.f;
#pragma unroll 8
    for (int k = 0; k < kE; ++k)
        acc = fmaf(sh[k], W2w[(size_t)k * kA + n], acc);
    g_ph[b * kA + n] = acc + W2b[n];
}

// ---------------------------------------------------------------------------
// 2) fused scores GEMM (fp16 m16n8k16 via ldmatrix) + packed tanh*V epilogue
//    CTA: 128 rows x 256 threads (8 warps = 4M x 2N), 2 CTAs/SM.
// ---------------------------------------------------------------------------
__device__ __forceinline__ void load_tile(char* smem, uint32_t base,
                                          const __half* g, int k0, int tid) {
#pragma unroll
    for (int i = 0; i < 4; ++i) {
        const int idx = tid + i * 256;
        const int r = idx >> 3, c = idx & 7;
        cp16(smem + base + (uint32_t)r * ROW_BYTES + c * 16,
             g + (size_t)r * kE + k0 + c * 8);
    }
}

__global__ void __launch_bounds__(256, 2)
scores_kernel(const float* __restrict__ W1b,
              const float* __restrict__ Vw,
              const float* __restrict__ Vb) {
    extern __shared__ char smem[];
    const uint32_t sbase = smem_u32(smem);
    uint32_t* cb = (uint32_t*)(smem + CB_OFF);
    uint32_t* vw = (uint32_t*)(smem + VW_OFF);
    float* srow  = (float*)(smem + SROW_OFF);

    const int tid = threadIdx.x;
    const int m_base = blockIdx.x * MT;
    const int b = m_base >> 10;

    {
        const float2* wb2 = (const float2*)W1b;
        const float2* ph2 = (const float2*)(g_ph + b * kA);
        const float2* vv2 = (const float2*)Vw;
        for (int i = tid; i < kA / 2; i += 256) {
            float2 a = wb2[i], p = ph2[i], v = vv2[i];
            __half2 hc = __floats2half2_rn(a.x + p.x, a.y + p.y);
            __half2 hv = __floats2half2_rn(v.x, v.y);
            cb[i] = *(uint32_t*)&hc;
            vw[i] = *(uint32_t*)&hv;
        }
    }
    if (tid < MT) srow[tid] = 0.f;
    __syncthreads();

    const int warp = tid >> 5, lane = tid & 31;
    const int wm = warp >> 1;   // 0..3 -> M offset wm*32
    const int wn = warp & 1;    // 0..1 -> N offset wn*64
    const int qc = lane & 3;    // threadID-in-group (epilogue col pair)

    // ldmatrix base addresses (byte offsets into shared space)
    // A (mt tiles): matrices [m0-7,k0][m8-15,k0][m0-7,k8][m8-15,k8]
    uint32_t aAddr[2];
#pragma unroll
    for (int mt = 0; mt < 2; ++mt)
        aAddr[mt] = sbase + SA_OFF +
                    (uint32_t)(wm * 32 + mt * 16 + (lane & 15)) * ROW_BYTES +
                    ((lane >> 4) * 8) * 2;
    // B (nn pairs): matrices [n0-7,k0][n0-7,k8][n8-15,k0][n8-15,k8]
    uint32_t bAddr[4];
#pragma unroll
    for (int nn = 0; nn < 4; ++nn)
        bAddr[nn] = sbase + SB_OFF +
                    (uint32_t)(wn * 64 + nn * 16 + ((lane >> 4) & 1) * 8 + (lane & 7)) * ROW_BYTES +
                    (((lane >> 3) & 1) * 8) * 2;

    const __half* gA = g_fA + (size_t)m_base * kE;

    float sc[2][2] = {{0.f, 0.f}, {0.f, 0.f}};

    for (int nb = 0; nb < NB; ++nb) {
        const int n0 = nb * NT;
        const __half* gB = g_W1t + (size_t)n0 * kE;

        float acc[2][8][4];
#pragma unroll
        for (int mt = 0; mt < 2; ++mt)
#pragma unroll
            for (int nt = 0; nt < 8; ++nt)
#pragma unroll
                for (int f = 0; f < 4; ++f) acc[mt][nt][f] = 0.f;

        // prologue: k-tile 0 -> buffer 0
        load_tile(smem, SA_OFF, gA, 0, tid);
        load_tile(smem, SB_OFF, gB, 0, tid);
        cp_commit();

        for (int kt = 0; kt < KTILES; ++kt) {
            const int buf = kt & 1;
            if (kt + 1 < KTILES) {
                const int k0 = (kt + 1) * KT;
                load_tile(smem, SA_OFF + (buf ^ 1) * TILE_B, gA, k0, tid);
                load_tile(smem, SB_OFF + (buf ^ 1) * TILE_B, gB, k0, tid);
                cp_commit();
                cp_wait<1>();
            } else {
                cp_wait<0>();
            }
            __syncthreads();

            const uint32_t bofs = (uint32_t)buf * TILE_B;
#pragma unroll
            for (int ks = 0; ks < 4; ++ks) {
                uint32_t a[2][4];
                ldsm4(a[0][0], a[0][1], a[0][2], a[0][3], aAddr[0] + bofs + ks * 32);
                ldsm4(a[1][0], a[1][1], a[1][2], a[1][3], aAddr[1] + bofs + ks * 32);
#pragma unroll
                for (int nn = 0; nn < 4; ++nn) {
                    uint32_t b0, b1, b2, b3;
                    ldsm4(b0, b1, b2, b3, bAddr[nn] + bofs + ks * 32);
                    mma_f16(acc[0][2 * nn],     a[0], b0, b1);
                    mma_f16(acc[1][2 * nn],     a[1], b0, b1);
                    mma_f16(acc[0][2 * nn + 1], a[0], b2, b3);
                    mma_f16(acc[1][2 * nn + 1], a[1], b2, b3);
                }
            }
            __syncthreads();
        }

        // epilogue: packed tanh + dot with V
#pragma unroll
        for (int mt = 0; mt < 2; ++mt) {
#pragma unroll
            for (int nt = 0; nt < 8; ++nt) {
                const int nh = (n0 + wn * 64 + nt * 8 + qc * 2) >> 1;
                const uint32_t ch = cb[nh];
                const uint32_t vh = vw[nh];
                sc[mt][0] += tanhv2(acc[mt][nt][0], acc[mt][nt][1], ch, vh);
                sc[mt][1] += tanhv2(acc[mt][nt][2], acc[mt][nt][3], ch, vh);
            }
        }
    }

    // reduce over quad columns, then across the 2 N-warps via smem atomics
    const int qr = lane >> 2;
#pragma unroll
    for (int mt = 0; mt < 2; ++mt)
#pragma unroll
        for (int h = 0; h < 2; ++h) {
            float v = sc[mt][h];
            v += __shfl_xor_sync(0xffffffffu, v, 1);
            v += __shfl_xor_sync(0xffffffffu, v, 2);
            if (qc == 0) atomicAdd(&srow[wm * 32 + mt * 16 + h * 8 + qr], v);
        }
    __syncthreads();
    if (tid < MT) g_scores[m_base + tid] = srow[tid] + Vb[0];
}

// ---------------------------------------------------------------------------
// 3) softmax over L per batch -> alpha
// ---------------------------------------------------------------------------
__global__ void softmax_kernel(float* __restrict__ alpha) {
    const int b = blockIdx.x;
    const int tid = threadIdx.x;
    const float* s = g_scores + b * kL;

    float v[4];
    float m = -1e30f;
#pragma unroll
    for (int i = 0; i < 4; ++i) {
        v[i] = s[tid + i * 256];
        m = fmaxf(m, v[i]);
    }
#pragma unroll
    for (int o = 16; o > 0; o >>= 1) m = fmaxf(m, __shfl_xor_sync(0xffffffffu, m, o));
    __shared__ float redm[8];
    __shared__ float reds[8];
    if ((tid & 31) == 0) redm[tid >> 5] = m;
    __syncthreads();
    m = redm[0];
#pragma unroll
    for (int i = 1; i < 8; ++i) m = fmaxf(m, redm[i]);

    float sum = 0.f;
#pragma unroll
    for (int i = 0; i < 4; ++i) {
        v[i] = expf(v[i] - m);
        sum += v[i];
    }
#pragma unroll
    for (int o = 16; o > 0; o >>= 1) sum += __shfl_xor_sync(0xffffffffu, sum, o);
    if ((tid & 31) == 0) reds[tid >> 5] = sum;
    __syncthreads();
    sum = 0.f;
#pragma unroll
    for (int i = 0; i < 8; ++i) sum += reds[i];
    const float inv = 1.f / sum;
#pragma unroll
    for (int i = 0; i < 4; ++i) alpha[b * kL + tid + i * 256] = v[i] * inv;
}

// ---------------------------------------------------------------------------
// 4a) context partials from fp16 features: 128 l-values per CTA
// ---------------------------------------------------------------------------
__global__ void __launch_bounds__(128)
context_part_kernel(const float* __restrict__ alpha) {
    const int chunk = blockIdx.x;   // 0..7
    const int b = blockIdx.y;
    __shared__ float sa[128];
    sa[threadIdx.x] = alpha[b * kL + chunk * 128 + threadIdx.x];
    __syncthreads();
    const uint4* f =
        (const uint4*)(g_fA + ((size_t)b * kL + chunk * 128) * kE) + threadIdx.x;
    float acc[8] = {0.f, 0.f, 0.f, 0.f, 0.f, 0.f, 0.f, 0.f};
#pragma unroll 4
    for (int l = 0; l < 128; ++l) {
        uint4 v = f[(size_t)l * (kE / 8)];
        const float a = sa[l];
        const __half2* h = (const __half2*)&v;
#pragma unroll
        for (int j = 0; j < 4; ++j) {
            float2 p = __half22float2(h[j]);
            acc[2 * j]     = fmaf(a, p.x, acc[2 * j]);
            acc[2 * j + 1] = fmaf(a, p.y, acc[2 * j + 1]);
        }
    }
    float* out = g_cpart + ((size_t)chunk * kB + b) * kE + threadIdx.x * 8;
    ((float4*)out)[0] = make_float4(acc[0], acc[1], acc[2], acc[3]);
    ((float4*)out)[1] = make_float4(acc[4], acc[5], acc[6], acc[7]);
}

// 4b) reduce the 8 partials -> context
__global__ void context_reduce_kernel(float* __restrict__ ctx) {
    const int b = blockIdx.y;
    const int e = blockIdx.x * 256 + threadIdx.x;
    float s = 0.f;
#pragma unroll
    for (int c = 0; c < 8; ++c) s += g_cpart[((size_t)c * kB + b) * kE + e];
    ctx[b * kE + e] = s;
}

// ---------------------------------------------------------------------------
// launch
// ---------------------------------------------------------------------------
extern "C" void kernel_launch(void* const* d_in, const int* in_sizes, int n_in,
                              void* d_out, int out_size) {
    (void)in_sizes; (void)n_in; (void)out_size;
    const float* features = (const float*)d_in[0];   // [B, L, ENC]
    const float* hidden   = (const float*)d_in[1];   // [B, DEC]
    const float* W1w      = (const float*)d_in[2];   // [ENC, ATT]
    const float* W1b      = (const float*)d_in[3];   // [ATT]
    const float* W2w      = (const float*)d_in[4];   // [DEC, ATT]
    const float* W2b      = (const float*)d_in[5];   // [ATT]
    const float* Vw       = (const float*)d_in[6];   // [ATT]
    const float* Vb       = (const float*)d_in[7];   // scalar

    float* out   = (float*)d_out;
    float* alpha = out;            // [B, L]
    float* ctx   = out + kB * kL;  // [B, ENC]

    cudaFuncSetAttribute(scores_kernel, cudaFuncAttributeMaxDynamicSharedMemorySize, SC_SMEM);

    conv_feat_kernel<<<4096, 256>>>((const float4*)features);
    conv_w1t_kernel<<<dim3(kA / 32, kE / 32), dim3(32, 32)>>>(W1w);
    proj_h_kernel<<<kB, 1024>>>(hidden, W2w, W2b);
    scores_kernel<<<kM / MT, 256, SC_SMEM>>>(W1b, Vw, Vb);
    softmax_kernel<<<kB, 256>>>(alpha);
    context_part_kernel<<<dim3(8, kB), 128>>>(alpha);
    context_reduce_kernel<<<dim3(kE / 256, kB), 256>>>(ctx);
}